// round 2
// baseline (speedup 1.0000x reference)
#include <cuda_runtime.h>
#include <cstdint>

// Problem constants (shapes fixed by the reference).
#define ND 128                     // latent dim
static const int MAXN = 50000;

// Scratch (device globals; allocation-free rule).
__device__ float g_h0[MAXN * ND];   // x @ gcn_w
__device__ float g_h1[MAXN * ND];   // agg / ping
__device__ float g_h2[MAXN * ND];   // pong
__device__ float g_deg[MAXN];
__device__ float g_dinv[MAXN];

// ---------------------------------------------------------------------------
// Activations
// ---------------------------------------------------------------------------
template <int ACT>
__device__ __forceinline__ float actf(float y) {
    if (ACT == 0) return y;
    if (ACT == 1) return 1.0f / (1.0f + expf(-y));        // sigmoid
    // ACT == 2: softplus(y - 5) = max(t,0) + log1p(exp(-|t|))
    float t = y - 5.0f;
    return fmaxf(t, 0.0f) + log1pf(expf(-fabsf(t)));
}

// ---------------------------------------------------------------------------
// GEMM: Y[n,128] = act(X[n,128] @ W[128,128] + bias)
// Block = 64 rows x 128 cols, 256 threads, 8x4 register tile per thread.
// W fully resident in smem (64KB), X transposed in smem (32KB) so that the
// per-k x-loads are warp-broadcast LDS (all lanes of a warp share ty).
// ---------------------------------------------------------------------------
template <int ACT>
__global__ void __launch_bounds__(256) gemm128(
    const float* __restrict__ X, const float* __restrict__ W,
    const float* __restrict__ bias, float* __restrict__ Y, int n)
{
    extern __shared__ float smem[];
    float* Ws = smem;              // [128][128]
    float* Xt = smem + ND * ND;    // [128][64]  (k-major, transposed)

    const int t = threadIdx.x;
    const int row0 = blockIdx.x * 64;

    // Load W (4096 float4, 16 per thread, coalesced).
    float4* Wsv = reinterpret_cast<float4*>(Ws);
    const float4* Wgv = reinterpret_cast<const float4*>(W);
#pragma unroll
    for (int i = 0; i < 16; i++) Wsv[t + 256 * i] = Wgv[t + 256 * i];

    // Load X transposed: lane-varying rows -> conflict-free STS.
    const float4* Xgv = reinterpret_cast<const float4*>(X);
    const int lrow = t & 63;
    const int kq0 = t >> 6;
    const int grow = row0 + lrow;
#pragma unroll
    for (int i = 0; i < 8; i++) {
        int kq = kq0 + 4 * i;                 // float4 index along k (0..31)
        float4 v = make_float4(0.f, 0.f, 0.f, 0.f);
        if (grow < n) v = Xgv[(size_t)grow * 32 + kq];
        int k = kq * 4;
        Xt[(k + 0) * 64 + lrow] = v.x;
        Xt[(k + 1) * 64 + lrow] = v.y;
        Xt[(k + 2) * 64 + lrow] = v.z;
        Xt[(k + 3) * 64 + lrow] = v.w;
    }
    __syncthreads();

    const int tx = t & 31;   // col group: cols 4*tx .. 4*tx+3
    const int ty = t >> 5;   // row group: rows 8*ty .. 8*ty+7

    float acc[8][4];
#pragma unroll
    for (int r = 0; r < 8; r++)
#pragma unroll
        for (int c = 0; c < 4; c++) acc[r][c] = 0.0f;

    const float4* Xtv = reinterpret_cast<const float4*>(Xt);
#pragma unroll 8
    for (int k = 0; k < ND; k++) {
        float4 w = Wsv[k * 32 + tx];
        float4 xa = Xtv[k * 16 + 2 * ty];       // broadcast across warp
        float4 xb = Xtv[k * 16 + 2 * ty + 1];
        float xr[8] = {xa.x, xa.y, xa.z, xa.w, xb.x, xb.y, xb.z, xb.w};
#pragma unroll
        for (int r = 0; r < 8; r++) {
            acc[r][0] += xr[r] * w.x;
            acc[r][1] += xr[r] * w.y;
            acc[r][2] += xr[r] * w.z;
            acc[r][3] += xr[r] * w.w;
        }
    }

    float4 bv = make_float4(0.f, 0.f, 0.f, 0.f);
    if (bias) bv = reinterpret_cast<const float4*>(bias)[tx];

#pragma unroll
    for (int r = 0; r < 8; r++) {
        int gr = row0 + ty * 8 + r;
        if (gr < n) {
            float4 o;
            o.x = actf<ACT>(acc[r][0] + bv.x);
            o.y = actf<ACT>(acc[r][1] + bv.y);
            o.z = actf<ACT>(acc[r][2] + bv.z);
            o.w = actf<ACT>(acc[r][3] + bv.w);
            reinterpret_cast<float4*>(Y)[(size_t)gr * 32 + tx] = o;
        }
    }
}

// ---------------------------------------------------------------------------
// GCN pieces
// ---------------------------------------------------------------------------
__global__ void deg_init_kernel(float* deg, int n) {
    int i = blockIdx.x * blockDim.x + threadIdx.x;
    if (i < n) deg[i] = 1.0f;   // self-loop
}

__global__ void deg_accum_kernel(const int* __restrict__ col, float* deg, int E) {
    int e = blockIdx.x * blockDim.x + threadIdx.x;
    if (e < E) atomicAdd(&deg[col[e]], 1.0f);
}

__global__ void dinv_kernel(const float* __restrict__ deg, float* dinv, int n) {
    int i = blockIdx.x * blockDim.x + threadIdx.x;
    if (i < n) dinv[i] = rsqrtf(deg[i]);
}

// agg[i] = dinv[i]^2 * h0[i]  (initializes agg; scatter then accumulates onto it)
__global__ void selfloop_kernel(const float* __restrict__ h0,
                                const float* __restrict__ dinv,
                                float* __restrict__ agg, int n)
{
    int idx = blockIdx.x * blockDim.x + threadIdx.x;   // float4 index
    int total = n * 32;
    if (idx >= total) return;
    int i = idx >> 5;
    float s = dinv[i];
    s = s * s;
    float4 v = reinterpret_cast<const float4*>(h0)[idx];
    v.x *= s; v.y *= s; v.z *= s; v.w *= s;
    reinterpret_cast<float4*>(agg)[idx] = v;
}

// One warp per edge: agg[col] += dinv[row]*dinv[col] * h0[row]
__global__ void scatter_kernel(const int* __restrict__ row,
                               const int* __restrict__ col,
                               const float* __restrict__ h0,
                               const float* __restrict__ dinv,
                               float* __restrict__ agg, int E)
{
    int w = (blockIdx.x * blockDim.x + threadIdx.x) >> 5;
    int lane = threadIdx.x & 31;
    if (w >= E) return;
    int r = row[w];
    int c = col[w];
    float nrm = dinv[r] * dinv[c];
    float4 v = reinterpret_cast<const float4*>(h0 + (size_t)r * ND)[lane];
    float* dst = agg + (size_t)c * ND + lane * 4;
    atomicAdd(dst + 0, v.x * nrm);
    atomicAdd(dst + 1, v.y * nrm);
    atomicAdd(dst + 2, v.z * nrm);
    atomicAdd(dst + 3, v.w * nrm);
}

__global__ void bias_add_kernel(float* __restrict__ h, const float* __restrict__ b, int n) {
    int idx = blockIdx.x * blockDim.x + threadIdx.x;   // float4 index
    int total = n * 32;
    if (idx >= total) return;
    int cq = idx & 31;
    float4 v = reinterpret_cast<float4*>(h)[idx];
    float4 bb = reinterpret_cast<const float4*>(b)[cq];
    v.x += bb.x; v.y += bb.y; v.z += bb.z; v.w += bb.w;
    reinterpret_cast<float4*>(h)[idx] = v;
}

// ---------------------------------------------------------------------------
// Threefry-2x32 (JAX), 20 rounds, key = (0, 42)
// ---------------------------------------------------------------------------
__device__ __forceinline__ uint32_t rotl32(uint32_t x, int r) {
    return (x << r) | (x >> (32 - r));
}

__device__ __forceinline__ void threefry2x32(uint32_t k0, uint32_t k1,
                                             uint32_t x0, uint32_t x1,
                                             uint32_t& o0, uint32_t& o1)
{
    uint32_t ks0 = k0, ks1 = k1, ks2 = k0 ^ k1 ^ 0x1BD11BDAu;
    x0 += ks0; x1 += ks1;
#define TF_ROUND(r) { x0 += x1; x1 = rotl32(x1, r); x1 ^= x0; }
    TF_ROUND(13) TF_ROUND(15) TF_ROUND(26) TF_ROUND(6)
    x0 += ks1; x1 += ks2 + 1u;
    TF_ROUND(17) TF_ROUND(29) TF_ROUND(16) TF_ROUND(24)
    x0 += ks2; x1 += ks0 + 2u;
    TF_ROUND(13) TF_ROUND(15) TF_ROUND(26) TF_ROUND(6)
    x0 += ks0; x1 += ks1 + 3u;
    TF_ROUND(17) TF_ROUND(29) TF_ROUND(16) TF_ROUND(24)
    x0 += ks1; x1 += ks2 + 4u;
    TF_ROUND(13) TF_ROUND(15) TF_ROUND(26) TF_ROUND(6)
    x0 += ks2; x1 += ks0 + 5u;
#undef TF_ROUND
    o0 = x0; o1 = x1;
}

__device__ __forceinline__ float tf_uniform(uint32_t bits) {
    return __uint_as_float((bits >> 9) | 0x3f800000u) - 1.0f;
}

// z = mu + std * eps, eps = jax.random.uniform(key(42), (N,D))
// JAX >= 0.4.36 default (threefry_partitionable=True): per-element 64-bit
// counter i; cipher input (i>>32, i&0xffffffff) = (0, i) here; 32-bit output
// is the XOR of the two cipher words.
__global__ void z_kernel(const float* __restrict__ mu,
                         const float* __restrict__ stdv,
                         float* __restrict__ z, int total)
{
    int i = blockIdx.x * blockDim.x + threadIdx.x;
    if (i >= total) return;
    uint32_t o0, o1;
    threefry2x32(0u, 42u, 0u, (uint32_t)i, o0, o1);
    float u = tf_uniform(o0 ^ o1);
    z[i] = fmaf(stdv[i], u, mu[i]);
}

// ---------------------------------------------------------------------------
// Launcher
// ---------------------------------------------------------------------------
extern "C" void kernel_launch(void* const* d_in, const int* in_sizes, int n_in,
                              void* d_out, int out_size)
{
    const float* x      = (const float*)d_in[0];
    const int*   eidx   = (const int*)  d_in[1];
    const float* gcn_w  = (const float*)d_in[2];
    const float* gcn_b  = (const float*)d_in[3];
    const float* enc_w  = (const float*)d_in[4];
    const float* enc_b  = (const float*)d_in[5];
    const float* mean_w = (const float*)d_in[6];
    const float* mean_b = (const float*)d_in[7];
    const float* std_w  = (const float*)d_in[8];
    const float* std_b  = (const float*)d_in[9];
    float* out = (float*)d_out;

    const int n  = in_sizes[0] / ND;         // 50000
    const int E  = in_sizes[1] / 2;          // 800000
    const int NE = n * ND;                   // 6,400,000

    float *h0, *h1, *h2, *deg, *dinv;
    cudaGetSymbolAddress((void**)&h0,   g_h0);
    cudaGetSymbolAddress((void**)&h1,   g_h1);
    cudaGetSymbolAddress((void**)&h2,   g_h2);
    cudaGetSymbolAddress((void**)&deg,  g_deg);
    cudaGetSymbolAddress((void**)&dinv, g_dinv);

    const int SMEM = (ND * ND + ND * 64) * (int)sizeof(float);   // 98304
    cudaFuncSetAttribute(gemm128<0>, cudaFuncAttributeMaxDynamicSharedMemorySize, SMEM);
    cudaFuncSetAttribute(gemm128<1>, cudaFuncAttributeMaxDynamicSharedMemorySize, SMEM);
    cudaFuncSetAttribute(gemm128<2>, cudaFuncAttributeMaxDynamicSharedMemorySize, SMEM);

    const int gblocks = (n + 63) / 64;

    // 1) h0 = x @ gcn_w
    gemm128<0><<<gblocks, 256, SMEM>>>(x, gcn_w, nullptr, h0, n);

    // 2) degrees (targets + self-loop), dinv
    deg_init_kernel<<<(n + 255) / 256, 256>>>(deg, n);
    deg_accum_kernel<<<(E + 255) / 256, 256>>>(eidx + E, deg, E);
    dinv_kernel<<<(n + 255) / 256, 256>>>(deg, dinv, n);

    // 3) agg = dinv^2 * h0 (self-loop term), then scatter edges
    selfloop_kernel<<<(n * 32 + 255) / 256, 256>>>(h0, dinv, h1, n);
    {
        long long threads = (long long)E * 32;
        int blocks = (int)((threads + 255) / 256);
        scatter_kernel<<<blocks, 256>>>(eidx, eidx + E, h0, dinv, h1, E);
    }
    bias_add_kernel<<<(n * 32 + 255) / 256, 256>>>(h1, gcn_b, n);

    // 4) 5 encoder layers: h = sigmoid(h @ W_i + b_i), ping-pong h1<->h2
    gemm128<1><<<gblocks, 256, SMEM>>>(h1, enc_w + 0 * ND * ND, enc_b + 0 * ND, h2, n);
    gemm128<1><<<gblocks, 256, SMEM>>>(h2, enc_w + 1 * ND * ND, enc_b + 1 * ND, h1, n);
    gemm128<1><<<gblocks, 256, SMEM>>>(h1, enc_w + 2 * ND * ND, enc_b + 2 * ND, h2, n);
    gemm128<1><<<gblocks, 256, SMEM>>>(h2, enc_w + 3 * ND * ND, enc_b + 3 * ND, h1, n);
    gemm128<1><<<gblocks, 256, SMEM>>>(h1, enc_w + 4 * ND * ND, enc_b + 4 * ND, h2, n);

    // 5) heads: mu -> out[NE..2NE), std -> out[2NE..3NE)
    gemm128<0><<<gblocks, 256, SMEM>>>(h2, mean_w, mean_b, out + NE, n);
    gemm128<2><<<gblocks, 256, SMEM>>>(h2, std_w,  std_b,  out + 2 * NE, n);

    // 6) z = mu + std * eps(threefry, partitionable) -> out[0..NE)
    z_kernel<<<(NE + 255) / 256, 256>>>(out + NE, out + 2 * NE, out, NE);
}

// round 4
// speedup vs baseline: 1.7065x; 1.7065x over previous
#include <cuda_runtime.h>
#include <cuda_bf16.h>
#include <cstdint>

#define ND 128
static const int MAXN = 50000;
static const int MAXE = 800000;

// Scratch (device globals; allocation-free rule).
__device__ float g_h0[MAXN * ND];
__device__ float g_h1[MAXN * ND];
__device__ float g_h2[MAXN * ND];
__device__ float g_dinv[MAXN];
__device__ int   g_cnt[MAXN];
__device__ int   g_off[MAXN + 1];
__device__ int   g_cur[MAXN];
__device__ int   g_csr[MAXE];
__device__ int   g_bsum[128];

// ---------------------------------------------------------------------------
// Helpers
// ---------------------------------------------------------------------------
__device__ __forceinline__ uint32_t smem_u32(const void* p) {
    uint32_t a;
    asm("{ .reg .u64 t; cvta.to.shared.u64 t, %1; cvt.u32.u64 %0, t; }"
        : "=r"(a) : "l"(p));
    return a;
}

__device__ __forceinline__ void ldsm_x4(uint32_t& r0, uint32_t& r1,
                                        uint32_t& r2, uint32_t& r3, uint32_t addr) {
    asm volatile("ldmatrix.sync.aligned.m8n8.x4.shared.b16 {%0,%1,%2,%3}, [%4];"
                 : "=r"(r0), "=r"(r1), "=r"(r2), "=r"(r3) : "r"(addr));
}

__device__ __forceinline__ void mma16816(float& c0, float& c1, float& c2, float& c3,
                                         uint32_t a0, uint32_t a1, uint32_t a2, uint32_t a3,
                                         uint32_t b0, uint32_t b1) {
    asm volatile(
        "mma.sync.aligned.m16n8k16.row.col.f32.bf16.bf16.f32 "
        "{%0,%1,%2,%3}, {%4,%5,%6,%7}, {%8,%9}, {%0,%1,%2,%3};"
        : "+f"(c0), "+f"(c1), "+f"(c2), "+f"(c3)
        : "r"(a0), "r"(a1), "r"(a2), "r"(a3), "r"(b0), "r"(b1));
}

__device__ __forceinline__ uint32_t pack_bf16x2(__nv_bfloat16 a, __nv_bfloat16 b) {
    return (uint32_t)__bfloat16_as_ushort(a) |
           ((uint32_t)__bfloat16_as_ushort(b) << 16);
}

__device__ __forceinline__ float actf(float y, int act) {
    if (act == 1) return 1.0f / (1.0f + expf(-y));        // sigmoid
    if (act == 2) {                                       // softplus(y - 5)
        float t = y - 5.0f;
        return fmaxf(t, 0.0f) + log1pf(expf(-fabsf(t)));
    }
    return y;
}

// ---------------------------------------------------------------------------
// Tensor-core GEMM: Y[n,128] = act(X[n,128] @ W[128,128] + bias)
// bf16x3 split: X = Ahi+Alo, W^T = Bhi+Blo; D = Ahi*Bhi + Ahi*Blo + Alo*Bhi.
// CTA: 128 rows x 128 cols, 256 threads = 8 warps in 4x2; warp tile 32x64.
// SMEM: 4 matrices of [128][136] bf16 (272B row stride -> ldmatrix is
// bank-conflict-free without swizzle). mma.sync.m16n8k16.row.col.
// ---------------------------------------------------------------------------
#define LDA 136                      // padded row length in bf16 elems
#define MAT_BYTES (128 * LDA * 2)    // 34816
#define OFF_A_HI 0
#define OFF_A_LO (MAT_BYTES)
#define OFF_B_HI (2 * MAT_BYTES)
#define OFF_B_LO (3 * MAT_BYTES)
#define SMEM_TC  (4 * MAT_BYTES)     // 139264

__global__ void __launch_bounds__(256, 1)
gemm_tc(const float* __restrict__ X, const float* __restrict__ W,
        const float* __restrict__ bias, float* __restrict__ Y, int n, int act)
{
    extern __shared__ char smem[];
    const uint32_t sb = smem_u32(smem);
    const int t = threadIdx.x;
    const int lane = t & 31;
    const int wid = t >> 5;
    const int warp_m = wid >> 1;      // 0..3 -> rows 32*warp_m
    const int warp_n = wid & 1;       // 0..1 -> cols 64*warp_n
    const int row0 = blockIdx.x * 128;

    // ---- A: load X tile (fp32), split hi/lo bf16, store padded rows ----
    {
        const float4* Xg = reinterpret_cast<const float4*>(X + (size_t)row0 * ND);
#pragma unroll
        for (int it = 0; it < 16; it++) {
            int idx = t + it * 256;               // float4 idx in 128x32 grid
            int row = idx >> 5, kq = idx & 31;
            float4 v = make_float4(0.f, 0.f, 0.f, 0.f);
            if (row0 + row < n) v = Xg[(size_t)row * 32 + kq];
            __nv_bfloat16 h0 = __float2bfloat16(v.x), h1 = __float2bfloat16(v.y);
            __nv_bfloat16 h2 = __float2bfloat16(v.z), h3 = __float2bfloat16(v.w);
            __nv_bfloat16 l0 = __float2bfloat16(v.x - __bfloat162float(h0));
            __nv_bfloat16 l1 = __float2bfloat16(v.y - __bfloat162float(h1));
            __nv_bfloat16 l2 = __float2bfloat16(v.z - __bfloat162float(h2));
            __nv_bfloat16 l3 = __float2bfloat16(v.w - __bfloat162float(h3));
            uint32_t o = (uint32_t)row * (LDA * 2) + (uint32_t)kq * 8;
            *reinterpret_cast<uint2*>(smem + OFF_A_HI + o) =
                make_uint2(pack_bf16x2(h0, h1), pack_bf16x2(h2, h3));
            *reinterpret_cast<uint2*>(smem + OFF_A_LO + o) =
                make_uint2(pack_bf16x2(l0, l1), pack_bf16x2(l2, l3));
        }
    }

    // ---- B = W^T: row = output col (n), k along the row ----
    {
        const int nn = t & 127;
        const int k_base = (t >> 7) * 64;
#pragma unroll
        for (int k0 = 0; k0 < 64; k0 += 4) {
            int k = k_base + k0;
            float w0 = W[(k + 0) * ND + nn];
            float w1 = W[(k + 1) * ND + nn];
            float w2 = W[(k + 2) * ND + nn];
            float w3 = W[(k + 3) * ND + nn];
            __nv_bfloat16 h0 = __float2bfloat16(w0), h1 = __float2bfloat16(w1);
            __nv_bfloat16 h2 = __float2bfloat16(w2), h3 = __float2bfloat16(w3);
            __nv_bfloat16 l0 = __float2bfloat16(w0 - __bfloat162float(h0));
            __nv_bfloat16 l1 = __float2bfloat16(w1 - __bfloat162float(h1));
            __nv_bfloat16 l2 = __float2bfloat16(w2 - __bfloat162float(h2));
            __nv_bfloat16 l3 = __float2bfloat16(w3 - __bfloat162float(h3));
            uint32_t o = (uint32_t)nn * (LDA * 2) + (uint32_t)k * 2;
            *reinterpret_cast<uint2*>(smem + OFF_B_HI + o) =
                make_uint2(pack_bf16x2(h0, h1), pack_bf16x2(h2, h3));
            *reinterpret_cast<uint2*>(smem + OFF_B_LO + o) =
                make_uint2(pack_bf16x2(l0, l1), pack_bf16x2(l2, l3));
        }
    }
    __syncthreads();

    // ---- Accumulators: c[mt][nt][4] for warp tile 32x64 ----
    float c[2][8][4];
#pragma unroll
    for (int mt = 0; mt < 2; mt++)
#pragma unroll
        for (int nt = 0; nt < 8; nt++)
#pragma unroll
            for (int i = 0; i < 4; i++) c[mt][nt][i] = 0.0f;

    // ldmatrix lane addressing: row = base + (lane&15), k-half = (lane>>4)*8
    const uint32_t lrow = (uint32_t)(lane & 15);
    const uint32_t lkoff = (uint32_t)((lane >> 4) * 8) * 2;   // bytes
    const uint32_t a_base = sb + (uint32_t)(warp_m * 32) * (LDA * 2);
    const uint32_t b_base = sb + (uint32_t)(warp_n * 64) * (LDA * 2);

    const uint32_t termA[3] = {OFF_A_HI, OFF_A_HI, OFF_A_LO};
    const uint32_t termB[3] = {OFF_B_HI, OFF_B_LO, OFF_B_HI};

    for (int term = 0; term < 3; term++) {
        const uint32_t Ab = a_base + termA[term] + lrow * (LDA * 2) + lkoff;
        const uint32_t Bb = b_base + termB[term] + lrow * (LDA * 2) + lkoff;
#pragma unroll
        for (int ks = 0; ks < 8; ks++) {
            const uint32_t kb = (uint32_t)(ks * 16) * 2;   // byte offset along k
            uint32_t a[2][4];
#pragma unroll
            for (int mt = 0; mt < 2; mt++)
                ldsm_x4(a[mt][0], a[mt][1], a[mt][2], a[mt][3],
                        Ab + (uint32_t)(mt * 16) * (LDA * 2) + kb);
            uint32_t b[4][4];
#pragma unroll
            for (int q = 0; q < 4; q++)
                ldsm_x4(b[q][0], b[q][1], b[q][2], b[q][3],
                        Bb + (uint32_t)(q * 16) * (LDA * 2) + kb);
#pragma unroll
            for (int mt = 0; mt < 2; mt++)
#pragma unroll
                for (int nt = 0; nt < 8; nt++) {
                    uint32_t b0 = b[nt >> 1][nt & 1];
                    uint32_t b1 = b[nt >> 1][(nt & 1) + 2];
                    mma16816(c[mt][nt][0], c[mt][nt][1], c[mt][nt][2], c[mt][nt][3],
                             a[mt][0], a[mt][1], a[mt][2], a[mt][3], b0, b1);
                }
        }
    }

    // ---- Epilogue: c0,c1 -> (row lane/4, cols 2*(lane%4)); c2,c3 -> row+8 ----
    {
        const int rbase = row0 + warp_m * 32 + (lane >> 2);
        const int cbase = warp_n * 64 + (lane & 3) * 2;
#pragma unroll
        for (int mt = 0; mt < 2; mt++) {
#pragma unroll
            for (int half = 0; half < 2; half++) {
                int row = rbase + mt * 16 + half * 8;
                if (row < n) {
                    float* Yr = Y + (size_t)row * ND;
#pragma unroll
                    for (int nt = 0; nt < 8; nt++) {
                        int col = cbase + nt * 8;
                        float b0 = 0.f, b1 = 0.f;
                        if (bias) {
                            float2 bb = *reinterpret_cast<const float2*>(bias + col);
                            b0 = bb.x; b1 = bb.y;
                        }
                        float2 o;
                        o.x = actf(c[mt][nt][2 * half + 0] + b0, act);
                        o.y = actf(c[mt][nt][2 * half + 1] + b1, act);
                        *reinterpret_cast<float2*>(Yr + col) = o;
                    }
                }
            }
        }
    }
}

// ---------------------------------------------------------------------------
// GCN aggregation: CSR build + warp-per-node gather
// ---------------------------------------------------------------------------
__global__ void cnt_zero_kernel(int* cnt, int n) {
    int i = blockIdx.x * blockDim.x + threadIdx.x;
    if (i < n) cnt[i] = 0;
}

__global__ void cnt_accum_kernel(const int* __restrict__ col, int* cnt, int E) {
    int e = blockIdx.x * blockDim.x + threadIdx.x;
    if (e < E) atomicAdd(&cnt[col[e]], 1);
}

// Per-block exclusive scan over 1024 elements (256 threads x 4).
__global__ void scan1_kernel(const int* __restrict__ cnt, int* __restrict__ off,
                             int* __restrict__ bsum, int n) {
    __shared__ int ts[256];
    int t = threadIdx.x;
    int base = blockIdx.x * 1024 + t * 4;
    int v0 = (base + 0 < n) ? cnt[base + 0] : 0;
    int v1 = (base + 1 < n) ? cnt[base + 1] : 0;
    int v2 = (base + 2 < n) ? cnt[base + 2] : 0;
    int v3 = (base + 3 < n) ? cnt[base + 3] : 0;
    ts[t] = v0 + v1 + v2 + v3;
    __syncthreads();
    for (int d = 1; d < 256; d <<= 1) {
        int x = (t >= d) ? ts[t - d] : 0;
        __syncthreads();
        ts[t] += x;
        __syncthreads();
    }
    int run = (t > 0) ? ts[t - 1] : 0;
    if (base + 0 < n) off[base + 0] = run;  run += v0;
    if (base + 1 < n) off[base + 1] = run;  run += v1;
    if (base + 2 < n) off[base + 2] = run;  run += v2;
    if (base + 3 < n) off[base + 3] = run;
    if (t == 255) bsum[blockIdx.x] = ts[255];
}

__global__ void scan2_kernel(int* bsum, int* off, int nblk, int n) {
    int run = 0;
    for (int i = 0; i < nblk; i++) {
        int v = bsum[i];
        bsum[i] = run;
        run += v;
    }
    off[n] = run;   // = E
}

__global__ void scan3_kernel(int* __restrict__ off, int* __restrict__ cur,
                             const int* __restrict__ cnt, const int* __restrict__ bsum,
                             float* __restrict__ dinv, int n) {
    int i = blockIdx.x * blockDim.x + threadIdx.x;
    if (i >= n) return;
    int o = off[i] + bsum[i >> 10];
    off[i] = o;
    cur[i] = o;
    dinv[i] = rsqrtf((float)cnt[i] + 1.0f);
}

__global__ void fill_kernel(const int* __restrict__ row, const int* __restrict__ col,
                            int* __restrict__ cur, int* __restrict__ csr, int E) {
    int e = blockIdx.x * blockDim.x + threadIdx.x;
    if (e >= E) return;
    int pos = atomicAdd(&cur[col[e]], 1);
    csr[pos] = row[e];
}

// Warp per node: h1[i] = dinv[i]^2*h0[i] + sum_e dinv[r]*dinv[i]*h0[r] + gcn_b
__global__ void gather_kernel(const float* __restrict__ h0,
                              const float* __restrict__ dinv,
                              const int* __restrict__ off,
                              const int* __restrict__ csr,
                              const float* __restrict__ b,
                              float* __restrict__ h1, int n)
{
    int w = (blockIdx.x * blockDim.x + threadIdx.x) >> 5;
    int lane = threadIdx.x & 31;
    if (w >= n) return;
    float di = dinv[w];
    const float4* H0 = reinterpret_cast<const float4*>(h0);
    float4 acc = H0[(size_t)w * 32 + lane];
    float dii = di * di;
    acc.x *= dii; acc.y *= dii; acc.z *= dii; acc.w *= dii;

    int j = off[w], end = off[w + 1];
    for (; j + 3 < end; j += 4) {
        int r0 = csr[j], r1 = csr[j + 1], r2 = csr[j + 2], r3 = csr[j + 3];
        float n0 = dinv[r0] * di, n1 = dinv[r1] * di;
        float n2 = dinv[r2] * di, n3 = dinv[r3] * di;
        float4 v0 = H0[(size_t)r0 * 32 + lane];
        float4 v1 = H0[(size_t)r1 * 32 + lane];
        float4 v2 = H0[(size_t)r2 * 32 + lane];
        float4 v3 = H0[(size_t)r3 * 32 + lane];
        acc.x += n0 * v0.x + n1 * v1.x + n2 * v2.x + n3 * v3.x;
        acc.y += n0 * v0.y + n1 * v1.y + n2 * v2.y + n3 * v3.y;
        acc.z += n0 * v0.z + n1 * v1.z + n2 * v2.z + n3 * v3.z;
        acc.w += n0 * v0.w + n1 * v1.w + n2 * v2.w + n3 * v3.w;
    }
    for (; j < end; j++) {
        int r = csr[j];
        float nr = dinv[r] * di;
        float4 v = H0[(size_t)r * 32 + lane];
        acc.x += nr * v.x; acc.y += nr * v.y; acc.z += nr * v.z; acc.w += nr * v.w;
    }
    float4 bb = reinterpret_cast<const float4*>(b)[lane];
    acc.x += bb.x; acc.y += bb.y; acc.z += bb.z; acc.w += bb.w;
    reinterpret_cast<float4*>(h1)[(size_t)w * 32 + lane] = acc;
}

// ---------------------------------------------------------------------------
// Threefry-2x32 (JAX partitionable), key = (0, 42)
// ---------------------------------------------------------------------------
__device__ __forceinline__ uint32_t rotl32(uint32_t x, int r) {
    return (x << r) | (x >> (32 - r));
}

__device__ __forceinline__ void threefry2x32(uint32_t k0, uint32_t k1,
                                             uint32_t x0, uint32_t x1,
                                             uint32_t& o0, uint32_t& o1)
{
    uint32_t ks0 = k0, ks1 = k1, ks2 = k0 ^ k1 ^ 0x1BD11BDAu;
    x0 += ks0; x1 += ks1;
#define TF_ROUND(r) { x0 += x1; x1 = rotl32(x1, r); x1 ^= x0; }
    TF_ROUND(13) TF_ROUND(15) TF_ROUND(26) TF_ROUND(6)
    x0 += ks1; x1 += ks2 + 1u;
    TF_ROUND(17) TF_ROUND(29) TF_ROUND(16) TF_ROUND(24)
    x0 += ks2; x1 += ks0 + 2u;
    TF_ROUND(13) TF_ROUND(15) TF_ROUND(26) TF_ROUND(6)
    x0 += ks0; x1 += ks1 + 3u;
    TF_ROUND(17) TF_ROUND(29) TF_ROUND(16) TF_ROUND(24)
    x0 += ks1; x1 += ks2 + 4u;
    TF_ROUND(13) TF_ROUND(15) TF_ROUND(26) TF_ROUND(6)
    x0 += ks2; x1 += ks0 + 5u;
#undef TF_ROUND
    o0 = x0; o1 = x1;
}

__global__ void z_kernel(const float* __restrict__ mu,
                         const float* __restrict__ stdv,
                         float* __restrict__ z, int total)
{
    int i = blockIdx.x * blockDim.x + threadIdx.x;
    if (i >= total) return;
    uint32_t o0, o1;
    threefry2x32(0u, 42u, 0u, (uint32_t)i, o0, o1);
    uint32_t bits = o0 ^ o1;
    float u = __uint_as_float((bits >> 9) | 0x3f800000u) - 1.0f;
    z[i] = fmaf(stdv[i], u, mu[i]);
}

// ---------------------------------------------------------------------------
// Launcher
// ---------------------------------------------------------------------------
extern "C" void kernel_launch(void* const* d_in, const int* in_sizes, int n_in,
                              void* d_out, int out_size)
{
    const float* x      = (const float*)d_in[0];
    const int*   eidx   = (const int*)  d_in[1];
    const float* gcn_w  = (const float*)d_in[2];
    const float* gcn_b  = (const float*)d_in[3];
    const float* enc_w  = (const float*)d_in[4];
    const float* enc_b  = (const float*)d_in[5];
    const float* mean_w = (const float*)d_in[6];
    const float* mean_b = (const float*)d_in[7];
    const float* std_w  = (const float*)d_in[8];
    const float* std_b  = (const float*)d_in[9];
    float* out = (float*)d_out;

    const int n  = in_sizes[0] / ND;          // 50000
    const int E  = in_sizes[1] / 2;           // 800000
    const int NE = n * ND;

    float *h0, *h1, *h2, *dinv;
    int *cnt, *off, *cur, *csr, *bsum;
    cudaGetSymbolAddress((void**)&h0,   g_h0);
    cudaGetSymbolAddress((void**)&h1,   g_h1);
    cudaGetSymbolAddress((void**)&h2,   g_h2);
    cudaGetSymbolAddress((void**)&dinv, g_dinv);
    cudaGetSymbolAddress((void**)&cnt,  g_cnt);
    cudaGetSymbolAddress((void**)&off,  g_off);
    cudaGetSymbolAddress((void**)&cur,  g_cur);
    cudaGetSymbolAddress((void**)&csr,  g_csr);
    cudaGetSymbolAddress((void**)&bsum, g_bsum);

    cudaFuncSetAttribute(gemm_tc, cudaFuncAttributeMaxDynamicSharedMemorySize, SMEM_TC);

    const int gblocks = (n + 127) / 128;
    const int nblk = (n + 1023) / 1024;

    // 1) h0 = x @ gcn_w
    gemm_tc<<<gblocks, 256, SMEM_TC>>>(x, gcn_w, nullptr, h0, n, 0);

    // 2) CSR build: counts -> scan -> fill; dinv fused into scan3
    cnt_zero_kernel <<<(n + 255) / 256, 256>>>(cnt, n);
    cnt_accum_kernel<<<(E + 255) / 256, 256>>>(eidx + E, cnt, E);
    scan1_kernel<<<nblk, 256>>>(cnt, off, bsum, n);
    scan2_kernel<<<1, 1>>>(bsum, off, nblk, n);
    scan3_kernel<<<(n + 255) / 256, 256>>>(off, cur, cnt, bsum, dinv, n);
    fill_kernel<<<(E + 255) / 256, 256>>>(eidx, eidx + E, cur, csr, E);

    // 3) gather: h1 = norm-aggregate(h0) + gcn_b
    gather_kernel<<<(n * 32 + 255) / 256, 256>>>(h0, dinv, off, csr, gcn_b, h1, n);

    // 4) encoder layers (sigmoid), ping-pong h1 <-> h2
    gemm_tc<<<gblocks, 256, SMEM_TC>>>(h1, enc_w + 0 * ND * ND, enc_b + 0 * ND, h2, n, 1);
    gemm_tc<<<gblocks, 256, SMEM_TC>>>(h2, enc_w + 1 * ND * ND, enc_b + 1 * ND, h1, n, 1);
    gemm_tc<<<gblocks, 256, SMEM_TC>>>(h1, enc_w + 2 * ND * ND, enc_b + 2 * ND, h2, n, 1);
    gemm_tc<<<gblocks, 256, SMEM_TC>>>(h2, enc_w + 3 * ND * ND, enc_b + 3 * ND, h1, n, 1);
    gemm_tc<<<gblocks, 256, SMEM_TC>>>(h1, enc_w + 4 * ND * ND, enc_b + 4 * ND, h2, n, 1);

    // 5) heads
    gemm_tc<<<gblocks, 256, SMEM_TC>>>(h2, mean_w, mean_b, out + NE,     n, 0);
    gemm_tc<<<gblocks, 256, SMEM_TC>>>(h2, std_w,  std_b,  out + 2 * NE, n, 2);

    // 6) z = mu + std * eps
    z_kernel<<<(NE + 255) / 256, 256>>>(out + NE, out + 2 * NE, out, NE);
}

// round 5
// speedup vs baseline: 1.7411x; 1.0203x over previous
#include <cuda_runtime.h>
#include <cuda_bf16.h>
#include <cstdint>

#define ND 128
static const int MAXN = 50000;
static const int MAXE = 800000;

#define LDA 136                       // padded row length (bf16 elems)
#define MAT_ELEMS (128 * LDA)         // 17408
#define MAT_BYTES (MAT_ELEMS * 2)     // 34816
#define NLAYER 8

// Scratch (device globals; allocation-free rule).
__device__ float g_h0[MAXN * ND];
__device__ float g_h1[MAXN * ND];
__device__ float g_h2[MAXN * ND];
__device__ float g_dinv[MAXN];
__device__ int   g_cnt[MAXN];
__device__ int   g_off[MAXN + 1];
__device__ int   g_cur[MAXN];
__device__ int   g_csr[MAXE];
__device__ int   g_bsum[128];
__device__ __align__(16) __nv_bfloat16 g_wsplit[NLAYER * 2 * MAT_ELEMS];

// ---------------------------------------------------------------------------
// Helpers
// ---------------------------------------------------------------------------
__device__ __forceinline__ uint32_t smem_u32(const void* p) {
    uint32_t a;
    asm("{ .reg .u64 t; cvta.to.shared.u64 t, %1; cvt.u32.u64 %0, t; }"
        : "=r"(a) : "l"(p));
    return a;
}

__device__ __forceinline__ void ldsm_x4(uint32_t& r0, uint32_t& r1,
                                        uint32_t& r2, uint32_t& r3, uint32_t addr) {
    asm volatile("ldmatrix.sync.aligned.m8n8.x4.shared.b16 {%0,%1,%2,%3}, [%4];"
                 : "=r"(r0), "=r"(r1), "=r"(r2), "=r"(r3) : "r"(addr));
}

__device__ __forceinline__ void mma16816(float& c0, float& c1, float& c2, float& c3,
                                         uint32_t a0, uint32_t a1, uint32_t a2, uint32_t a3,
                                         uint32_t b0, uint32_t b1) {
    asm volatile(
        "mma.sync.aligned.m16n8k16.row.col.f32.bf16.bf16.f32 "
        "{%0,%1,%2,%3}, {%4,%5,%6,%7}, {%8,%9}, {%0,%1,%2,%3};"
        : "+f"(c0), "+f"(c1), "+f"(c2), "+f"(c3)
        : "r"(a0), "r"(a1), "r"(a2), "r"(a3), "r"(b0), "r"(b1));
}

__device__ __forceinline__ uint32_t pack_bf16x2(__nv_bfloat16 a, __nv_bfloat16 b) {
    return (uint32_t)__bfloat16_as_ushort(a) |
           ((uint32_t)__bfloat16_as_ushort(b) << 16);
}

__device__ __forceinline__ float actf(float y, int act) {
    if (act == 1) return 1.0f / (1.0f + expf(-y));        // sigmoid
    if (act == 2) {                                       // softplus(y - 5)
        float t = y - 5.0f;
        return fmaxf(t, 0.0f) + log1pf(expf(-fabsf(t)));
    }
    return y;
}

// ---------------------------------------------------------------------------
// W prep: per layer l, W^T split hi/lo into padded ldmatrix layout.
//   dst[l][0][nn*LDA + k] = hi(W_l[k,nn]);  dst[l][1][...] = lo.
// Layers: 0=gcn, 1..5=enc[i], 6=mean, 7=std.
// ---------------------------------------------------------------------------
__global__ void wprep_kernel(const float* __restrict__ gcn,
                             const float* __restrict__ enc,
                             const float* __restrict__ meanw,
                             const float* __restrict__ stdw,
                             __nv_bfloat16* __restrict__ dst)
{
    int l = blockIdx.y;
    const float* W = (l == 0) ? gcn
                   : (l <= 5) ? enc + (l - 1) * ND * ND
                   : (l == 6) ? meanw : stdw;
    int i = blockIdx.x * blockDim.x + threadIdx.x;    // 0..16383
    int nn = i >> 7, k = i & 127;
    float w = W[k * ND + nn];
    __nv_bfloat16 hi = __float2bfloat16(w);
    __nv_bfloat16 lo = __float2bfloat16(w - __bfloat162float(hi));
    __nv_bfloat16* base = dst + (size_t)l * 2 * MAT_ELEMS;
    base[nn * LDA + k] = hi;
    base[MAT_ELEMS + nn * LDA + k] = lo;
}

// ---------------------------------------------------------------------------
// Tensor-core GEMM: Y[n,128] = act(X[n,128] @ W[128,128] + bias)
// bf16x3: D = Ahi*Bhi + Ahi*Blo + Alo*Bhi. CTA = 64 rows x 128 cols,
// 256 threads = 8 warps (2m x 4n), warp tile 32x32. B preconverted in global.
// smem: A_hi[64][136], A_lo, B_hi[128][136], B_lo  -> 104448 B, 2 CTAs/SM.
// ---------------------------------------------------------------------------
#define A_MAT_BYTES (64 * LDA * 2)    // 17408
#define OFF_A_HI 0
#define OFF_A_LO (A_MAT_BYTES)
#define OFF_B_HI (2 * A_MAT_BYTES)
#define OFF_B_LO (2 * A_MAT_BYTES + MAT_BYTES)
#define SMEM_TC  (2 * A_MAT_BYTES + 2 * MAT_BYTES)   // 104448

__global__ void __launch_bounds__(256, 2)
gemm_tc(const float* __restrict__ X, const __nv_bfloat16* __restrict__ Bpre,
        const float* __restrict__ bias, float* __restrict__ Y, int n, int act)
{
    extern __shared__ char smem[];
    const uint32_t sb = smem_u32(smem);
    const int t = threadIdx.x;
    const int lane = t & 31;
    const int wid = t >> 5;
    const int warp_m = wid >> 2;      // 0..1 -> rows 32*warp_m
    const int warp_n = wid & 3;       // 0..3 -> cols 32*warp_n
    const int row0 = blockIdx.x * 64;

    // ---- B: straight copy of preconverted hi/lo (layout matches smem) ----
    {
        const uint4* src = reinterpret_cast<const uint4*>(Bpre);
        uint4* dst = reinterpret_cast<uint4*>(smem + OFF_B_HI);
        // 2 * MAT_BYTES / 16 = 4352 uint4, 256 threads -> 17 each
#pragma unroll
        for (int i = 0; i < 17; i++) dst[t + 256 * i] = src[t + 256 * i];
    }

    // ---- A: load X tile (fp32), split hi/lo, store padded rows ----
    {
        const float4* Xg = reinterpret_cast<const float4*>(X + (size_t)row0 * ND);
#pragma unroll
        for (int it = 0; it < 8; it++) {
            int idx = t + it * 256;               // float4 idx in 64x32 grid
            int row = idx >> 5, kq = idx & 31;
            float4 v = make_float4(0.f, 0.f, 0.f, 0.f);
            if (row0 + row < n) v = Xg[(size_t)row * 32 + kq];
            __nv_bfloat16 h0 = __float2bfloat16(v.x), h1 = __float2bfloat16(v.y);
            __nv_bfloat16 h2 = __float2bfloat16(v.z), h3 = __float2bfloat16(v.w);
            __nv_bfloat16 l0 = __float2bfloat16(v.x - __bfloat162float(h0));
            __nv_bfloat16 l1 = __float2bfloat16(v.y - __bfloat162float(h1));
            __nv_bfloat16 l2 = __float2bfloat16(v.z - __bfloat162float(h2));
            __nv_bfloat16 l3 = __float2bfloat16(v.w - __bfloat162float(h3));
            uint32_t o = (uint32_t)row * (LDA * 2) + (uint32_t)kq * 8;
            *reinterpret_cast<uint2*>(smem + OFF_A_HI + o) =
                make_uint2(pack_bf16x2(h0, h1), pack_bf16x2(h2, h3));
            *reinterpret_cast<uint2*>(smem + OFF_A_LO + o) =
                make_uint2(pack_bf16x2(l0, l1), pack_bf16x2(l2, l3));
        }
    }
    __syncthreads();

    // ---- Accumulators: warp tile 32x32 -> c[2][4][4] ----
    float c[2][4][4];
#pragma unroll
    for (int mt = 0; mt < 2; mt++)
#pragma unroll
        for (int nt = 0; nt < 4; nt++)
#pragma unroll
            for (int i = 0; i < 4; i++) c[mt][nt][i] = 0.0f;

    const uint32_t lrow = (uint32_t)(lane & 15);
    const uint32_t lkoff = (uint32_t)((lane >> 4) * 8) * 2;   // bytes
    const uint32_t a_base = sb + (uint32_t)(warp_m * 32) * (LDA * 2);
    const uint32_t b_base = sb + (uint32_t)(warp_n * 32) * (LDA * 2);

    const uint32_t termA[3] = {OFF_A_HI, OFF_A_HI, OFF_A_LO};
    const uint32_t termB[3] = {OFF_B_HI, OFF_B_LO, OFF_B_HI};

    for (int term = 0; term < 3; term++) {
        const uint32_t Ab = a_base + termA[term] + lrow * (LDA * 2) + lkoff;
        const uint32_t Bb = b_base + termB[term] + lrow * (LDA * 2) + lkoff;
#pragma unroll
        for (int ks = 0; ks < 8; ks++) {
            const uint32_t kb = (uint32_t)(ks * 16) * 2;
            uint32_t a[2][4];
#pragma unroll
            for (int mt = 0; mt < 2; mt++)
                ldsm_x4(a[mt][0], a[mt][1], a[mt][2], a[mt][3],
                        Ab + (uint32_t)(mt * 16) * (LDA * 2) + kb);
            uint32_t b[2][4];
#pragma unroll
            for (int q = 0; q < 2; q++)
                ldsm_x4(b[q][0], b[q][1], b[q][2], b[q][3],
                        Bb + (uint32_t)(q * 16) * (LDA * 2) + kb);
#pragma unroll
            for (int mt = 0; mt < 2; mt++)
#pragma unroll
                for (int nt = 0; nt < 4; nt++) {
                    uint32_t b0 = b[nt >> 1][nt & 1];
                    uint32_t b1 = b[nt >> 1][(nt & 1) + 2];
                    mma16816(c[mt][nt][0], c[mt][nt][1], c[mt][nt][2], c[mt][nt][3],
                             a[mt][0], a[mt][1], a[mt][2], a[mt][3], b0, b1);
                }
        }
    }

    // ---- Epilogue ----
    {
        const int rbase = row0 + warp_m * 32 + (lane >> 2);
        const int cbase = warp_n * 32 + (lane & 3) * 2;
#pragma unroll
        for (int mt = 0; mt < 2; mt++) {
#pragma unroll
            for (int half = 0; half < 2; half++) {
                int row = rbase + mt * 16 + half * 8;
                if (row < n) {
                    float* Yr = Y + (size_t)row * ND;
#pragma unroll
                    for (int nt = 0; nt < 4; nt++) {
                        int col = cbase + nt * 8;
                        float b0 = 0.f, b1 = 0.f;
                        if (bias) {
                            float2 bb = *reinterpret_cast<const float2*>(bias + col);
                            b0 = bb.x; b1 = bb.y;
                        }
                        float2 o;
                        o.x = actf(c[mt][nt][2 * half + 0] + b0, act);
                        o.y = actf(c[mt][nt][2 * half + 1] + b1, act);
                        *reinterpret_cast<float2*>(Yr + col) = o;
                    }
                }
            }
        }
    }
}

// ---------------------------------------------------------------------------
// GCN aggregation: CSR build + warp-per-node gather
// ---------------------------------------------------------------------------
__global__ void cnt_zero_kernel(int* cnt, int n) {
    int i = blockIdx.x * blockDim.x + threadIdx.x;
    if (i < n) cnt[i] = 0;
}

__global__ void cnt_accum_kernel(const int* __restrict__ col, int* cnt, int E) {
    int e = blockIdx.x * blockDim.x + threadIdx.x;
    if (e < E) atomicAdd(&cnt[col[e]], 1);
}

__global__ void scan1_kernel(const int* __restrict__ cnt, int* __restrict__ off,
                             int* __restrict__ bsum, int n) {
    __shared__ int ts[256];
    int t = threadIdx.x;
    int base = blockIdx.x * 1024 + t * 4;
    int v0 = (base + 0 < n) ? cnt[base + 0] : 0;
    int v1 = (base + 1 < n) ? cnt[base + 1] : 0;
    int v2 = (base + 2 < n) ? cnt[base + 2] : 0;
    int v3 = (base + 3 < n) ? cnt[base + 3] : 0;
    ts[t] = v0 + v1 + v2 + v3;
    __syncthreads();
    for (int d = 1; d < 256; d <<= 1) {
        int x = (t >= d) ? ts[t - d] : 0;
        __syncthreads();
        ts[t] += x;
        __syncthreads();
    }
    int run = (t > 0) ? ts[t - 1] : 0;
    if (base + 0 < n) off[base + 0] = run;  run += v0;
    if (base + 1 < n) off[base + 1] = run;  run += v1;
    if (base + 2 < n) off[base + 2] = run;  run += v2;
    if (base + 3 < n) off[base + 3] = run;
    if (t == 255) bsum[blockIdx.x] = ts[255];
}

__global__ void scan2_kernel(int* bsum, int* off, int nblk, int n) {
    int run = 0;
    for (int i = 0; i < nblk; i++) {
        int v = bsum[i];
        bsum[i] = run;
        run += v;
    }
    off[n] = run;
}

__global__ void scan3_kernel(int* __restrict__ off, int* __restrict__ cur,
                             const int* __restrict__ cnt, const int* __restrict__ bsum,
                             float* __restrict__ dinv, int n) {
    int i = blockIdx.x * blockDim.x + threadIdx.x;
    if (i >= n) return;
    int o = off[i] + bsum[i >> 10];
    off[i] = o;
    cur[i] = o;
    dinv[i] = rsqrtf((float)cnt[i] + 1.0f);
}

__global__ void fill_kernel(const int* __restrict__ row, const int* __restrict__ col,
                            int* __restrict__ cur, int* __restrict__ csr, int E) {
    int e = blockIdx.x * blockDim.x + threadIdx.x;
    if (e >= E) return;
    int pos = atomicAdd(&cur[col[e]], 1);
    csr[pos] = row[e];
}

__global__ void gather_kernel(const float* __restrict__ h0,
                              const float* __restrict__ dinv,
                              const int* __restrict__ off,
                              const int* __restrict__ csr,
                              const float* __restrict__ b,
                              float* __restrict__ h1, int n)
{
    int w = (blockIdx.x * blockDim.x + threadIdx.x) >> 5;
    int lane = threadIdx.x & 31;
    if (w >= n) return;
    float di = dinv[w];
    const float4* H0 = reinterpret_cast<const float4*>(h0);
    float4 acc = H0[(size_t)w * 32 + lane];
    float dii = di * di;
    acc.x *= dii; acc.y *= dii; acc.z *= dii; acc.w *= dii;

    int j = off[w], end = off[w + 1];
    for (; j + 3 < end; j += 4) {
        int r0 = csr[j], r1 = csr[j + 1], r2 = csr[j + 2], r3 = csr[j + 3];
        float n0 = dinv[r0] * di, n1 = dinv[r1] * di;
        float n2 = dinv[r2] * di, n3 = dinv[r3] * di;
        float4 v0 = H0[(size_t)r0 * 32 + lane];
        float4 v1 = H0[(size_t)r1 * 32 + lane];
        float4 v2 = H0[(size_t)r2 * 32 + lane];
        float4 v3 = H0[(size_t)r3 * 32 + lane];
        acc.x += n0 * v0.x + n1 * v1.x + n2 * v2.x + n3 * v3.x;
        acc.y += n0 * v0.y + n1 * v1.y + n2 * v2.y + n3 * v3.y;
        acc.z += n0 * v0.z + n1 * v1.z + n2 * v2.z + n3 * v3.z;
        acc.w += n0 * v0.w + n1 * v1.w + n2 * v2.w + n3 * v3.w;
    }
    for (; j < end; j++) {
        int r = csr[j];
        float nr = dinv[r] * di;
        float4 v = H0[(size_t)r * 32 + lane];
        acc.x += nr * v.x; acc.y += nr * v.y; acc.z += nr * v.z; acc.w += nr * v.w;
    }
    float4 bb = reinterpret_cast<const float4*>(b)[lane];
    acc.x += bb.x; acc.y += bb.y; acc.z += bb.z; acc.w += bb.w;
    reinterpret_cast<float4*>(h1)[(size_t)w * 32 + lane] = acc;
}

// ---------------------------------------------------------------------------
// Threefry-2x32 (JAX partitionable), key = (0, 42)
// ---------------------------------------------------------------------------
__device__ __forceinline__ uint32_t rotl32(uint32_t x, int r) {
    return (x << r) | (x >> (32 - r));
}

__device__ __forceinline__ void threefry2x32(uint32_t k0, uint32_t k1,
                                             uint32_t x0, uint32_t x1,
                                             uint32_t& o0, uint32_t& o1)
{
    uint32_t ks0 = k0, ks1 = k1, ks2 = k0 ^ k1 ^ 0x1BD11BDAu;
    x0 += ks0; x1 += ks1;
#define TF_ROUND(r) { x0 += x1; x1 = rotl32(x1, r); x1 ^= x0; }
    TF_ROUND(13) TF_ROUND(15) TF_ROUND(26) TF_ROUND(6)
    x0 += ks1; x1 += ks2 + 1u;
    TF_ROUND(17) TF_ROUND(29) TF_ROUND(16) TF_ROUND(24)
    x0 += ks2; x1 += ks0 + 2u;
    TF_ROUND(13) TF_ROUND(15) TF_ROUND(26) TF_ROUND(6)
    x0 += ks0; x1 += ks1 + 3u;
    TF_ROUND(17) TF_ROUND(29) TF_ROUND(16) TF_ROUND(24)
    x0 += ks1; x1 += ks2 + 4u;
    TF_ROUND(13) TF_ROUND(15) TF_ROUND(26) TF_ROUND(6)
    x0 += ks2; x1 += ks0 + 5u;
#undef TF_ROUND
    o0 = x0; o1 = x1;
}

__global__ void z_kernel(const float* __restrict__ mu,
                         const float* __restrict__ stdv,
                         float* __restrict__ z, int total)
{
    int i = blockIdx.x * blockDim.x + threadIdx.x;
    if (i >= total) return;
    uint32_t o0, o1;
    threefry2x32(0u, 42u, 0u, (uint32_t)i, o0, o1);
    uint32_t bits = o0 ^ o1;
    float u = __uint_as_float((bits >> 9) | 0x3f800000u) - 1.0f;
    z[i] = fmaf(stdv[i], u, mu[i]);
}

// ---------------------------------------------------------------------------
// Launcher
// ---------------------------------------------------------------------------
extern "C" void kernel_launch(void* const* d_in, const int* in_sizes, int n_in,
                              void* d_out, int out_size)
{
    const float* x      = (const float*)d_in[0];
    const int*   eidx   = (const int*)  d_in[1];
    const float* gcn_w  = (const float*)d_in[2];
    const float* gcn_b  = (const float*)d_in[3];
    const float* enc_w  = (const float*)d_in[4];
    const float* enc_b  = (const float*)d_in[5];
    const float* mean_w = (const float*)d_in[6];
    const float* mean_b = (const float*)d_in[7];
    const float* std_w  = (const float*)d_in[8];
    const float* std_b  = (const float*)d_in[9];
    float* out = (float*)d_out;

    const int n  = in_sizes[0] / ND;          // 50000
    const int E  = in_sizes[1] / 2;           // 800000
    const int NE = n * ND;

    float *h0, *h1, *h2, *dinv;
    int *cnt, *off, *cur, *csr, *bsum;
    __nv_bfloat16* ws;
    cudaGetSymbolAddress((void**)&h0,   g_h0);
    cudaGetSymbolAddress((void**)&h1,   g_h1);
    cudaGetSymbolAddress((void**)&h2,   g_h2);
    cudaGetSymbolAddress((void**)&dinv, g_dinv);
    cudaGetSymbolAddress((void**)&cnt,  g_cnt);
    cudaGetSymbolAddress((void**)&off,  g_off);
    cudaGetSymbolAddress((void**)&cur,  g_cur);
    cudaGetSymbolAddress((void**)&csr,  g_csr);
    cudaGetSymbolAddress((void**)&bsum, g_bsum);
    cudaGetSymbolAddress((void**)&ws,   g_wsplit);

    cudaFuncSetAttribute(gemm_tc, cudaFuncAttributeMaxDynamicSharedMemorySize, SMEM_TC);

    const int gblocks = (n + 63) / 64;        // 782
    const int nblk = (n + 1023) / 1024;

    // 0) preconvert all 8 weight matrices (W^T hi/lo, ldmatrix layout)
    {
        dim3 grid(ND * ND / 256, NLAYER);
        wprep_kernel<<<grid, 256>>>(gcn_w, enc_w, mean_w, std_w, ws);
    }
#define WL(l) (ws + (size_t)(l) * 2 * MAT_ELEMS)

    // 1) h0 = x @ gcn_w
    gemm_tc<<<gblocks, 256, SMEM_TC>>>(x, WL(0), nullptr, h0, n, 0);

    // 2) CSR build: counts -> scan -> fill; dinv fused into scan3
    cnt_zero_kernel <<<(n + 255) / 256, 256>>>(cnt, n);
    cnt_accum_kernel<<<(E + 255) / 256, 256>>>(eidx + E, cnt, E);
    scan1_kernel<<<nblk, 256>>>(cnt, off, bsum, n);
    scan2_kernel<<<1, 1>>>(bsum, off, nblk, n);
    scan3_kernel<<<(n + 255) / 256, 256>>>(off, cur, cnt, bsum, dinv, n);
    fill_kernel<<<(E + 255) / 256, 256>>>(eidx, eidx + E, cur, csr, E);

    // 3) gather: h1 = norm-aggregate(h0) + gcn_b
    gather_kernel<<<(n * 32 + 255) / 256, 256>>>(h0, dinv, off, csr, gcn_b, h1, n);

    // 4) encoder layers (sigmoid), ping-pong h1 <-> h2
    gemm_tc<<<gblocks, 256, SMEM_TC>>>(h1, WL(1), enc_b + 0 * ND, h2, n, 1);
    gemm_tc<<<gblocks, 256, SMEM_TC>>>(h2, WL(2), enc_b + 1 * ND, h1, n, 1);
    gemm_tc<<<gblocks, 256, SMEM_TC>>>(h1, WL(3), enc_b + 2 * ND, h2, n, 1);
    gemm_tc<<<gblocks, 256, SMEM_TC>>>(h2, WL(4), enc_b + 3 * ND, h1, n, 1);
    gemm_tc<<<gblocks, 256, SMEM_TC>>>(h1, WL(5), enc_b + 4 * ND, h2, n, 1);

    // 5) heads
    gemm_tc<<<gblocks, 256, SMEM_TC>>>(h2, WL(6), mean_b, out + NE,     n, 0);
    gemm_tc<<<gblocks, 256, SMEM_TC>>>(h2, WL(7), std_b,  out + 2 * NE, n, 2);

    // 6) z = mu + std * eps
    z_kernel<<<(NE + 255) / 256, 256>>>(out + NE, out + 2 * NE, out, NE);
}

// round 6
// speedup vs baseline: 2.3549x; 1.3525x over previous
#include <cuda_runtime.h>
#include <cuda_fp16.h>
#include <cstdint>

#define ND 128
static const int MAXN = 50000;
static const int MAXE = 800000;

#define LDA 136                       // padded row length (fp16 elems)
#define MAT_ELEMS (128 * LDA)         // 17408
#define MAT_BYTES (MAT_ELEMS * 2)     // 34816
#define NLAYER 8

// Scratch (device globals; allocation-free rule).
__device__ float g_h0[MAXN * ND];
__device__ float g_h1[MAXN * ND];
__device__ float g_h2[MAXN * ND];
__device__ float g_dinv[MAXN];
__device__ int   g_cnt[MAXN];
__device__ int   g_off[MAXN + 1];
__device__ int   g_cur[MAXN];
__device__ int   g_csr[MAXE];
__device__ int   g_bsum[128];
__device__ __align__(16) __half g_wsplit[NLAYER * 2 * MAT_ELEMS];

// ---------------------------------------------------------------------------
// Helpers
// ---------------------------------------------------------------------------
__device__ __forceinline__ uint32_t smem_u32(const void* p) {
    uint32_t a;
    asm("{ .reg .u64 t; cvta.to.shared.u64 t, %1; cvt.u32.u64 %0, t; }"
        : "=r"(a) : "l"(p));
    return a;
}

__device__ __forceinline__ void ldsm_x4(uint32_t& r0, uint32_t& r1,
                                        uint32_t& r2, uint32_t& r3, uint32_t addr) {
    asm volatile("ldmatrix.sync.aligned.m8n8.x4.shared.b16 {%0,%1,%2,%3}, [%4];"
                 : "=r"(r0), "=r"(r1), "=r"(r2), "=r"(r3) : "r"(addr));
}

__device__ __forceinline__ void mma16816(float& c0, float& c1, float& c2, float& c3,
                                         uint32_t a0, uint32_t a1, uint32_t a2, uint32_t a3,
                                         uint32_t b0, uint32_t b1) {
    asm volatile(
        "mma.sync.aligned.m16n8k16.row.col.f32.f16.f16.f32 "
        "{%0,%1,%2,%3}, {%4,%5,%6,%7}, {%8,%9}, {%0,%1,%2,%3};"
        : "+f"(c0), "+f"(c1), "+f"(c2), "+f"(c3)
        : "r"(a0), "r"(a1), "r"(a2), "r"(a3), "r"(b0), "r"(b1));
}

__device__ __forceinline__ uint32_t pack_h2(float a, float b) {
    __half ha = __float2half_rn(a), hb = __float2half_rn(b);
    return (uint32_t)__half_as_ushort(ha) |
           ((uint32_t)__half_as_ushort(hb) << 16);
}

__device__ __forceinline__ float actf(float y, int act) {
    if (act == 1) return 1.0f / (1.0f + expf(-y));        // sigmoid
    if (act == 2) {                                       // softplus(y - 5)
        float t = y - 5.0f;
        return fmaxf(t, 0.0f) + log1pf(expf(-fabsf(t)));
    }
    return y;
}

// ---------------------------------------------------------------------------
// W prep: per layer l, W^T split into fp16 hi/lo, padded ldmatrix layout.
// Layers: 0=gcn, 1..5=enc[i], 6=mean, 7=std.
// ---------------------------------------------------------------------------
__global__ void wprep_kernel(const float* __restrict__ gcn,
                             const float* __restrict__ enc,
                             const float* __restrict__ meanw,
                             const float* __restrict__ stdw,
                             __half* __restrict__ dst)
{
    int l = blockIdx.y;
    const float* W = (l == 0) ? gcn
                   : (l <= 5) ? enc + (l - 1) * ND * ND
                   : (l == 6) ? meanw : stdw;
    int i = blockIdx.x * blockDim.x + threadIdx.x;    // 0..16383
    int nn = i >> 7, k = i & 127;
    float w = W[k * ND + nn];
    __half hi = __float2half_rn(w);
    __half lo = __float2half_rn(w - __half2float(hi));
    __half* base = dst + (size_t)l * 2 * MAT_ELEMS;
    base[nn * LDA + k] = hi;
    base[MAT_ELEMS + nn * LDA + k] = lo;
}

// ---------------------------------------------------------------------------
// 2-term fp16 GEMM: Y = act(X @ W + b); D = Ahi*Bhi + Ahi*Blo.
// Dropped xlo*w term: ~2^-12 rel per product (inner layers only; damped).
// CTA 64x128, 256 thr, 8 warps (2m x 4n), warp tile 32x32.
// smem: A_hi[64][136] + B_hi[128][136] + B_lo -> 87040 B, 2 CTAs/SM.
// ---------------------------------------------------------------------------
#define G2_A_HI 0
#define G2_B_HI 17408
#define G2_B_LO (17408 + MAT_BYTES)
#define SMEM_G2 (17408 + 2 * MAT_BYTES)   // 87040

__global__ void __launch_bounds__(256, 2)
gemm_2t(const float* __restrict__ X, const __half* __restrict__ Bpre,
        const float* __restrict__ bias, float* __restrict__ Y, int n, int act)
{
    extern __shared__ char smem[];
    const uint32_t sb = smem_u32(smem);
    const int t = threadIdx.x;
    const int lane = t & 31;
    const int wid = t >> 5;
    const int warp_m = wid >> 2;
    const int warp_n = wid & 3;
    const int row0 = blockIdx.x * 64;

    // B: copy preconverted hi+lo (contiguous, layout matches smem)
    {
        const uint4* src = reinterpret_cast<const uint4*>(Bpre);
        uint4* dst = reinterpret_cast<uint4*>(smem + G2_B_HI);
#pragma unroll
        for (int i = 0; i < 17; i++) dst[t + 256 * i] = src[t + 256 * i];
    }

    // A: load X tile, fp16 hi only
    {
        const float4* Xg = reinterpret_cast<const float4*>(X + (size_t)row0 * ND);
#pragma unroll
        for (int it = 0; it < 8; it++) {
            int idx = t + it * 256;
            int row = idx >> 5, kq = idx & 31;
            float4 v = make_float4(0.f, 0.f, 0.f, 0.f);
            if (row0 + row < n) v = Xg[(size_t)row * 32 + kq];
            uint32_t o = (uint32_t)row * (LDA * 2) + (uint32_t)kq * 8;
            *reinterpret_cast<uint2*>(smem + G2_A_HI + o) =
                make_uint2(pack_h2(v.x, v.y), pack_h2(v.z, v.w));
        }
    }
    __syncthreads();

    float c[2][4][4];
#pragma unroll
    for (int mt = 0; mt < 2; mt++)
#pragma unroll
        for (int nt = 0; nt < 4; nt++)
#pragma unroll
            for (int i = 0; i < 4; i++) c[mt][nt][i] = 0.0f;

    const uint32_t lrow = (uint32_t)(lane & 15);
    const uint32_t lkoff = (uint32_t)((lane >> 4) * 8) * 2;
    const uint32_t a_base = sb + (uint32_t)(warp_m * 32) * (LDA * 2);
    const uint32_t b_base = sb + (uint32_t)(warp_n * 32) * (LDA * 2);

    const uint32_t termB[2] = {G2_B_HI, G2_B_LO};

    for (int term = 0; term < 2; term++) {
        const uint32_t Ab = a_base + G2_A_HI + lrow * (LDA * 2) + lkoff;
        const uint32_t Bb = b_base + termB[term] + lrow * (LDA * 2) + lkoff;
#pragma unroll
        for (int ks = 0; ks < 8; ks++) {
            const uint32_t kb = (uint32_t)(ks * 16) * 2;
            uint32_t a[2][4];
#pragma unroll
            for (int mt = 0; mt < 2; mt++)
                ldsm_x4(a[mt][0], a[mt][1], a[mt][2], a[mt][3],
                        Ab + (uint32_t)(mt * 16) * (LDA * 2) + kb);
            uint32_t b[2][4];
#pragma unroll
            for (int q = 0; q < 2; q++)
                ldsm_x4(b[q][0], b[q][1], b[q][2], b[q][3],
                        Bb + (uint32_t)(q * 16) * (LDA * 2) + kb);
#pragma unroll
            for (int mt = 0; mt < 2; mt++)
#pragma unroll
                for (int nt = 0; nt < 4; nt++) {
                    uint32_t b0 = b[nt >> 1][nt & 1];
                    uint32_t b1 = b[nt >> 1][(nt & 1) + 2];
                    mma16816(c[mt][nt][0], c[mt][nt][1], c[mt][nt][2], c[mt][nt][3],
                             a[mt][0], a[mt][1], a[mt][2], a[mt][3], b0, b1);
                }
        }
    }

    {
        const int rbase = row0 + warp_m * 32 + (lane >> 2);
        const int cbase = warp_n * 32 + (lane & 3) * 2;
#pragma unroll
        for (int mt = 0; mt < 2; mt++) {
#pragma unroll
            for (int half = 0; half < 2; half++) {
                int row = rbase + mt * 16 + half * 8;
                if (row < n) {
                    float* Yr = Y + (size_t)row * ND;
#pragma unroll
                    for (int nt = 0; nt < 4; nt++) {
                        int col = cbase + nt * 8;
                        float b0 = 0.f, b1 = 0.f;
                        if (bias) {
                            float2 bb = *reinterpret_cast<const float2*>(bias + col);
                            b0 = bb.x; b1 = bb.y;
                        }
                        float2 o;
                        o.x = actf(c[mt][nt][2 * half + 0] + b0, act);
                        o.y = actf(c[mt][nt][2 * half + 1] + b1, act);
                        *reinterpret_cast<float2*>(Yr + col) = o;
                    }
                }
            }
        }
    }
}

// ---------------------------------------------------------------------------
// Threefry-2x32 (JAX partitionable), key = (0, 42)
// ---------------------------------------------------------------------------
__device__ __forceinline__ uint32_t rotl32(uint32_t x, int r) {
    return (x << r) | (x >> (32 - r));
}

__device__ __forceinline__ float tf_uniform(uint32_t i) {
    uint32_t x0 = 0u, x1 = i;
    const uint32_t k0 = 0u, k1 = 42u, k2 = 0u ^ 42u ^ 0x1BD11BDAu;
    x0 += k0; x1 += k1;
#define TF_ROUND(r) { x0 += x1; x1 = rotl32(x1, r); x1 ^= x0; }
    TF_ROUND(13) TF_ROUND(15) TF_ROUND(26) TF_ROUND(6)
    x0 += k1; x1 += k2 + 1u;
    TF_ROUND(17) TF_ROUND(29) TF_ROUND(16) TF_ROUND(24)
    x0 += k2; x1 += k0 + 2u;
    TF_ROUND(13) TF_ROUND(15) TF_ROUND(26) TF_ROUND(6)
    x0 += k0; x1 += k1 + 3u;
    TF_ROUND(17) TF_ROUND(29) TF_ROUND(16) TF_ROUND(24)
    x0 += k1; x1 += k2 + 4u;
    TF_ROUND(13) TF_ROUND(15) TF_ROUND(26) TF_ROUND(6)
    x0 += k2; x1 += k0 + 5u;
#undef TF_ROUND
    uint32_t bits = x0 ^ x1;
    return __uint_as_float((bits >> 9) | 0x3f800000u) - 1.0f;
}

// ---------------------------------------------------------------------------
// Fused heads + z: mu = h2@Wm + bm ; std = softplus(h2@Ws + bs - 5);
// z = mu + std * u(i). 3-term fp16 per head (residual ~2^-22).
// CTA 64 rows, 256 thr, 1 CTA/SM (174080 B smem).
// ---------------------------------------------------------------------------
#define HD_A_HI 0
#define HD_A_LO 17408
#define HD_BM_HI 34816
#define HD_BM_LO (34816 + MAT_BYTES)
#define HD_BS_HI (34816 + 2 * MAT_BYTES)
#define HD_BS_LO (34816 + 3 * MAT_BYTES)
#define SMEM_HD (34816 + 4 * MAT_BYTES)   // 174080

__global__ void __launch_bounds__(256, 1)
heads_z(const float* __restrict__ X,
        const __half* __restrict__ BmPre, const __half* __restrict__ BsPre,
        const float* __restrict__ bm, const float* __restrict__ bs,
        float* __restrict__ zo, float* __restrict__ muo, float* __restrict__ sto,
        int n)
{
    extern __shared__ char smem[];
    const uint32_t sb = smem_u32(smem);
    const int t = threadIdx.x;
    const int lane = t & 31;
    const int wid = t >> 5;
    const int warp_m = wid >> 2;
    const int warp_n = wid & 3;
    const int row0 = blockIdx.x * 64;

    // B: copy both heads' hi+lo
    {
        const uint4* srcm = reinterpret_cast<const uint4*>(BmPre);
        const uint4* srcs = reinterpret_cast<const uint4*>(BsPre);
        uint4* dstm = reinterpret_cast<uint4*>(smem + HD_BM_HI);
        uint4* dsts = reinterpret_cast<uint4*>(smem + HD_BS_HI);
#pragma unroll
        for (int i = 0; i < 17; i++) {
            dstm[t + 256 * i] = srcm[t + 256 * i];
            dsts[t + 256 * i] = srcs[t + 256 * i];
        }
    }

    // A: load h2 tile, split fp16 hi/lo
    {
        const float4* Xg = reinterpret_cast<const float4*>(X + (size_t)row0 * ND);
#pragma unroll
        for (int it = 0; it < 8; it++) {
            int idx = t + it * 256;
            int row = idx >> 5, kq = idx & 31;
            float4 v = make_float4(0.f, 0.f, 0.f, 0.f);
            if (row0 + row < n) v = Xg[(size_t)row * 32 + kq];
            __half h0 = __float2half_rn(v.x), h1 = __float2half_rn(v.y);
            __half h2 = __float2half_rn(v.z), h3 = __float2half_rn(v.w);
            float l0 = v.x - __half2float(h0), l1 = v.y - __half2float(h1);
            float l2 = v.z - __half2float(h2), l3 = v.w - __half2float(h3);
            uint32_t o = (uint32_t)row * (LDA * 2) + (uint32_t)kq * 8;
            uint32_t hi01 = (uint32_t)__half_as_ushort(h0) |
                            ((uint32_t)__half_as_ushort(h1) << 16);
            uint32_t hi23 = (uint32_t)__half_as_ushort(h2) |
                            ((uint32_t)__half_as_ushort(h3) << 16);
            *reinterpret_cast<uint2*>(smem + HD_A_HI + o) = make_uint2(hi01, hi23);
            *reinterpret_cast<uint2*>(smem + HD_A_LO + o) =
                make_uint2(pack_h2(l0, l1), pack_h2(l2, l3));
        }
    }
    __syncthreads();

    float cm[2][4][4], cs[2][4][4];
#pragma unroll
    for (int mt = 0; mt < 2; mt++)
#pragma unroll
        for (int nt = 0; nt < 4; nt++)
#pragma unroll
            for (int i = 0; i < 4; i++) { cm[mt][nt][i] = 0.0f; cs[mt][nt][i] = 0.0f; }

    const uint32_t lrow = (uint32_t)(lane & 15);
    const uint32_t lkoff = (uint32_t)((lane >> 4) * 8) * 2;
    const uint32_t a_base = sb + (uint32_t)(warp_m * 32) * (LDA * 2);
    const uint32_t b_base = sb + (uint32_t)(warp_n * 32) * (LDA * 2);

    const uint32_t termA[3]  = {HD_A_HI, HD_A_HI, HD_A_LO};
    const uint32_t termBm[3] = {HD_BM_HI, HD_BM_LO, HD_BM_HI};
    const uint32_t termBs[3] = {HD_BS_HI, HD_BS_LO, HD_BS_HI};

    for (int term = 0; term < 3; term++) {
        const uint32_t Ab  = a_base + termA[term]  + lrow * (LDA * 2) + lkoff;
        const uint32_t Bmb = b_base + termBm[term] + lrow * (LDA * 2) + lkoff;
        const uint32_t Bsb = b_base + termBs[term] + lrow * (LDA * 2) + lkoff;
#pragma unroll
        for (int ks = 0; ks < 8; ks++) {
            const uint32_t kb = (uint32_t)(ks * 16) * 2;
            uint32_t a[2][4];
#pragma unroll
            for (int mt = 0; mt < 2; mt++)
                ldsm_x4(a[mt][0], a[mt][1], a[mt][2], a[mt][3],
                        Ab + (uint32_t)(mt * 16) * (LDA * 2) + kb);
            uint32_t bmf[2][4], bsf[2][4];
#pragma unroll
            for (int q = 0; q < 2; q++) {
                ldsm_x4(bmf[q][0], bmf[q][1], bmf[q][2], bmf[q][3],
                        Bmb + (uint32_t)(q * 16) * (LDA * 2) + kb);
                ldsm_x4(bsf[q][0], bsf[q][1], bsf[q][2], bsf[q][3],
                        Bsb + (uint32_t)(q * 16) * (LDA * 2) + kb);
            }
#pragma unroll
            for (int mt = 0; mt < 2; mt++)
#pragma unroll
                for (int nt = 0; nt < 4; nt++) {
                    uint32_t m0 = bmf[nt >> 1][nt & 1];
                    uint32_t m1 = bmf[nt >> 1][(nt & 1) + 2];
                    mma16816(cm[mt][nt][0], cm[mt][nt][1], cm[mt][nt][2], cm[mt][nt][3],
                             a[mt][0], a[mt][1], a[mt][2], a[mt][3], m0, m1);
                    uint32_t s0 = bsf[nt >> 1][nt & 1];
                    uint32_t s1 = bsf[nt >> 1][(nt & 1) + 2];
                    mma16816(cs[mt][nt][0], cs[mt][nt][1], cs[mt][nt][2], cs[mt][nt][3],
                             a[mt][0], a[mt][1], a[mt][2], a[mt][3], s0, s1);
                }
        }
    }

    // Epilogue: mu, std, z
    {
        const int rbase = row0 + warp_m * 32 + (lane >> 2);
        const int cbase = warp_n * 32 + (lane & 3) * 2;
#pragma unroll
        for (int mt = 0; mt < 2; mt++) {
#pragma unroll
            for (int half = 0; half < 2; half++) {
                int row = rbase + mt * 16 + half * 8;
                if (row < n) {
#pragma unroll
                    for (int nt = 0; nt < 4; nt++) {
                        int col = cbase + nt * 8;
                        float2 bbm = *reinterpret_cast<const float2*>(bm + col);
                        float2 bbs = *reinterpret_cast<const float2*>(bs + col);
                        float mu0 = cm[mt][nt][2 * half + 0] + bbm.x;
                        float mu1 = cm[mt][nt][2 * half + 1] + bbm.y;
                        float s0 = actf(cs[mt][nt][2 * half + 0] + bbs.x, 2);
                        float s1 = actf(cs[mt][nt][2 * half + 1] + bbs.y, 2);
                        uint32_t i0 = (uint32_t)row * ND + (uint32_t)col;
                        float u0 = tf_uniform(i0);
                        float u1 = tf_uniform(i0 + 1);
                        size_t p = (size_t)row * ND + col;
                        *reinterpret_cast<float2*>(muo + p) = make_float2(mu0, mu1);
                        *reinterpret_cast<float2*>(sto + p) = make_float2(s0, s1);
                        *reinterpret_cast<float2*>(zo + p) =
                            make_float2(fmaf(s0, u0, mu0), fmaf(s1, u1, mu1));
                    }
                }
            }
        }
    }
}

// ---------------------------------------------------------------------------
// GCN aggregation: CSR build + warp-per-node gather (unchanged)
// ---------------------------------------------------------------------------
__global__ void cnt_zero_kernel(int* cnt, int n) {
    int i = blockIdx.x * blockDim.x + threadIdx.x;
    if (i < n) cnt[i] = 0;
}

__global__ void cnt_accum_kernel(const int* __restrict__ col, int* cnt, int E) {
    int e = blockIdx.x * blockDim.x + threadIdx.x;
    if (e < E) atomicAdd(&cnt[col[e]], 1);
}

__global__ void scan1_kernel(const int* __restrict__ cnt, int* __restrict__ off,
                             int* __restrict__ bsum, int n) {
    __shared__ int ts[256];
    int t = threadIdx.x;
    int base = blockIdx.x * 1024 + t * 4;
    int v0 = (base + 0 < n) ? cnt[base + 0] : 0;
    int v1 = (base + 1 < n) ? cnt[base + 1] : 0;
    int v2 = (base + 2 < n) ? cnt[base + 2] : 0;
    int v3 = (base + 3 < n) ? cnt[base + 3] : 0;
    ts[t] = v0 + v1 + v2 + v3;
    __syncthreads();
    for (int d = 1; d < 256; d <<= 1) {
        int x = (t >= d) ? ts[t - d] : 0;
        __syncthreads();
        ts[t] += x;
        __syncthreads();
    }
    int run = (t > 0) ? ts[t - 1] : 0;
    if (base + 0 < n) off[base + 0] = run;  run += v0;
    if (base + 1 < n) off[base + 1] = run;  run += v1;
    if (base + 2 < n) off[base + 2] = run;  run += v2;
    if (base + 3 < n) off[base + 3] = run;
    if (t == 255) bsum[blockIdx.x] = ts[255];
}

__global__ void scan2_kernel(int* bsum, int* off, int nblk, int n) {
    int run = 0;
    for (int i = 0; i < nblk; i++) {
        int v = bsum[i];
        bsum[i] = run;
        run += v;
    }
    off[n] = run;
}

__global__ void scan3_kernel(int* __restrict__ off, int* __restrict__ cur,
                             const int* __restrict__ cnt, const int* __restrict__ bsum,
                             float* __restrict__ dinv, int n) {
    int i = blockIdx.x * blockDim.x + threadIdx.x;
    if (i >= n) return;
    int o = off[i] + bsum[i >> 10];
    off[i] = o;
    cur[i] = o;
    dinv[i] = rsqrtf((float)cnt[i] + 1.0f);
}

__global__ void fill_kernel(const int* __restrict__ row, const int* __restrict__ col,
                            int* __restrict__ cur, int* __restrict__ csr, int E) {
    int e = blockIdx.x * blockDim.x + threadIdx.x;
    if (e >= E) return;
    int pos = atomicAdd(&cur[col[e]], 1);
    csr[pos] = row[e];
}

__global__ void gather_kernel(const float* __restrict__ h0,
                              const float* __restrict__ dinv,
                              const int* __restrict__ off,
                              const int* __restrict__ csr,
                              const float* __restrict__ b,
                              float* __restrict__ h1, int n)
{
    int w = (blockIdx.x * blockDim.x + threadIdx.x) >> 5;
    int lane = threadIdx.x & 31;
    if (w >= n) return;
    float di = dinv[w];
    const float4* H0 = reinterpret_cast<const float4*>(h0);
    float4 acc = H0[(size_t)w * 32 + lane];
    float dii = di * di;
    acc.x *= dii; acc.y *= dii; acc.z *= dii; acc.w *= dii;

    int j = off[w], end = off[w + 1];
    for (; j + 3 < end; j += 4) {
        int r0 = csr[j], r1 = csr[j + 1], r2 = csr[j + 2], r3 = csr[j + 3];
        float n0 = dinv[r0] * di, n1 = dinv[r1] * di;
        float n2 = dinv[r2] * di, n3 = dinv[r3] * di;
        float4 v0 = H0[(size_t)r0 * 32 + lane];
        float4 v1 = H0[(size_t)r1 * 32 + lane];
        float4 v2 = H0[(size_t)r2 * 32 + lane];
        float4 v3 = H0[(size_t)r3 * 32 + lane];
        acc.x += n0 * v0.x + n1 * v1.x + n2 * v2.x + n3 * v3.x;
        acc.y += n0 * v0.y + n1 * v1.y + n2 * v2.y + n3 * v3.y;
        acc.z += n0 * v0.z + n1 * v1.z + n2 * v2.z + n3 * v3.z;
        acc.w += n0 * v0.w + n1 * v1.w + n2 * v2.w + n3 * v3.w;
    }
    for (; j < end; j++) {
        int r = csr[j];
        float nr = dinv[r] * di;
        float4 v = H0[(size_t)r * 32 + lane];
        acc.x += nr * v.x; acc.y += nr * v.y; acc.z += nr * v.z; acc.w += nr * v.w;
    }
    float4 bb = reinterpret_cast<const float4*>(b)[lane];
    acc.x += bb.x; acc.y += bb.y; acc.z += bb.z; acc.w += bb.w;
    reinterpret_cast<float4*>(h1)[(size_t)w * 32 + lane] = acc;
}

// ---------------------------------------------------------------------------
// Launcher
// ---------------------------------------------------------------------------
extern "C" void kernel_launch(void* const* d_in, const int* in_sizes, int n_in,
                              void* d_out, int out_size)
{
    const float* x      = (const float*)d_in[0];
    const int*   eidx   = (const int*)  d_in[1];
    const float* gcn_w  = (const float*)d_in[2];
    const float* gcn_b  = (const float*)d_in[3];
    const float* enc_w  = (const float*)d_in[4];
    const float* enc_b  = (const float*)d_in[5];
    const float* mean_w = (const float*)d_in[6];
    const float* mean_b = (const float*)d_in[7];
    const float* std_w  = (const float*)d_in[8];
    const float* std_b  = (const float*)d_in[9];
    float* out = (float*)d_out;

    const int n  = in_sizes[0] / ND;          // 50000
    const int E  = in_sizes[1] / 2;           // 800000
    const int NE = n * ND;

    float *h0, *h1, *h2, *dinv;
    int *cnt, *off, *cur, *csr, *bsum;
    __half* ws;
    cudaGetSymbolAddress((void**)&h0,   g_h0);
    cudaGetSymbolAddress((void**)&h1,   g_h1);
    cudaGetSymbolAddress((void**)&h2,   g_h2);
    cudaGetSymbolAddress((void**)&dinv, g_dinv);
    cudaGetSymbolAddress((void**)&cnt,  g_cnt);
    cudaGetSymbolAddress((void**)&off,  g_off);
    cudaGetSymbolAddress((void**)&cur,  g_cur);
    cudaGetSymbolAddress((void**)&csr,  g_csr);
    cudaGetSymbolAddress((void**)&bsum, g_bsum);
    cudaGetSymbolAddress((void**)&ws,   g_wsplit);

    cudaFuncSetAttribute(gemm_2t, cudaFuncAttributeMaxDynamicSharedMemorySize, SMEM_G2);
    cudaFuncSetAttribute(heads_z, cudaFuncAttributeMaxDynamicSharedMemorySize, SMEM_HD);

    const int gblocks = (n + 63) / 64;        // 782
    const int nblk = (n + 1023) / 1024;

#define WL(l) (ws + (size_t)(l) * 2 * MAT_ELEMS)

    // Fork: CSR build on side stream, overlapping wprep + GEMM0.
    cudaStream_t s2;
    cudaStreamCreateWithFlags(&s2, cudaStreamNonBlocking);
    cudaEvent_t ev1, ev2;
    cudaEventCreateWithFlags(&ev1, cudaEventDisableTiming);
    cudaEventCreateWithFlags(&ev2, cudaEventDisableTiming);

    cudaEventRecord(ev1, 0);
    cudaStreamWaitEvent(s2, ev1, 0);
    cnt_zero_kernel <<<(n + 255) / 256, 256, 0, s2>>>(cnt, n);
    cnt_accum_kernel<<<(E + 255) / 256, 256, 0, s2>>>(eidx + E, cnt, E);
    scan1_kernel<<<nblk, 256, 0, s2>>>(cnt, off, bsum, n);
    scan2_kernel<<<1, 1, 0, s2>>>(bsum, off, nblk, n);
    scan3_kernel<<<(n + 255) / 256, 256, 0, s2>>>(off, cur, cnt, bsum, dinv, n);
    fill_kernel<<<(E + 255) / 256, 256, 0, s2>>>(eidx, eidx + E, cur, csr, E);
    cudaEventRecord(ev2, s2);

    // Main stream: weight prep + GEMM0 concurrently with CSR build.
    {
        dim3 grid(ND * ND / 256, NLAYER);
        wprep_kernel<<<grid, 256>>>(gcn_w, enc_w, mean_w, std_w, ws);
    }
    gemm_2t<<<gblocks, 256, SMEM_G2>>>(x, WL(0), nullptr, h0, n, 0);

    // Join, then gather.
    cudaStreamWaitEvent(0, ev2, 0);
    gather_kernel<<<(n * 32 + 255) / 256, 256>>>(h0, dinv, off, csr, gcn_b, h1, n);

    // Encoder layers (sigmoid), ping-pong h1 <-> h2.
    gemm_2t<<<gblocks, 256, SMEM_G2>>>(h1, WL(1), enc_b + 0 * ND, h2, n, 1);
    gemm_2t<<<gblocks, 256, SMEM_G2>>>(h2, WL(2), enc_b + 1 * ND, h1, n, 1);
    gemm_2t<<<gblocks, 256, SMEM_G2>>>(h1, WL(3), enc_b + 2 * ND, h2, n, 1);
    gemm_2t<<<gblocks, 256, SMEM_G2>>>(h2, WL(4), enc_b + 3 * ND, h1, n, 1);
    gemm_2t<<<gblocks, 256, SMEM_G2>>>(h1, WL(5), enc_b + 4 * ND, h2, n, 1);

    // Fused heads + z.
    heads_z<<<gblocks, 256, SMEM_HD>>>(h2, WL(6), WL(7), mean_b, std_b,
                                       out, out + NE, out + 2 * NE, n);

    cudaEventDestroy(ev1);
    cudaEventDestroy(ev2);
    cudaStreamDestroy(s2);
}